// round 2
// baseline (speedup 1.0000x reference)
#include <cuda_runtime.h>

// FFT-based circular convolution:  y[b,h,:] = irfft(rfft(x[b,h]) * rfft(k[h]))
// B=8, H=768, L=N=4096, fp32.
//
// Strategy:
//   * Complex 4096-point FFT in shared memory, radix-8, 512 threads, 8 pts/thread.
//   * Pack two batch rows (same h) as real+imag of ONE complex FFT. Because K[h]
//     is conjugate-symmetric, ifft((X0+iX1)*K) = y0 + i*y1 directly (no unpack).
//   * Forward DIF leaves digit-reversed layout; Kf is computed by the SAME code
//     path and stored in the same layout, so the pointwise multiply is trivially
//     consistent. Inverse is the exact pipeline mirror (conj twiddles, reversed
//     exchange order) -> natural-order output. No bit-reversal pass.
//   * pad(i)=i+(i>>3) makes all 4 exchange patterns bank-conflict-free
//     (verified per half-warp phase for 8-byte accesses).

#define NFFT 4096
#define NTHR 512
#define HDIM 768
#define BDIM 8

// Scratch: K spectra in pipeline layout. 768*4096 float2 = 25.2 MB.
__device__ float2 g_kf[HDIM * NFFT];

__device__ __forceinline__ float2 cadd(float2 a, float2 b) {
    return make_float2(a.x + b.x, a.y + b.y);
}
__device__ __forceinline__ float2 csub(float2 a, float2 b) {
    return make_float2(a.x - b.x, a.y - b.y);
}
__device__ __forceinline__ float2 cmul(float2 a, float2 b) {
    return make_float2(fmaf(a.x, b.x, -a.y * b.y), fmaf(a.x, b.y, a.y * b.x));
}
// multiply by -i / +i
__device__ __forceinline__ float2 mulmi(float2 a) { return make_float2(a.y, -a.x); }
__device__ __forceinline__ float2 mulpi(float2 a) { return make_float2(-a.y, a.x); }

// smem padding: +1 slot per 8 -> all exchange patterns conflict-free
__device__ __forceinline__ int pad(int i) { return i + (i >> 3); }
#define SM_SZ (NFFT + (NFFT >> 3))   // 4608 float2 = 36 KB

// 8-point DFT, natural-order in and out. INV = conjugated twiddles (no 1/8).
template <bool INV>
__device__ __forceinline__ void dft8(float2 v[8]) {
    const float c = 0.70710678118654752f;
    float2 a0 = cadd(v[0], v[4]), a1 = cadd(v[1], v[5]);
    float2 a2 = cadd(v[2], v[6]), a3 = cadd(v[3], v[7]);
    float2 b0 = csub(v[0], v[4]), b1 = csub(v[1], v[5]);
    float2 b2 = csub(v[2], v[6]), b3 = csub(v[3], v[7]);
    // W8^1, W8^2, W8^3 (conjugated for INV)
    b1 = INV ? cmul(b1, make_float2(c, c)) : cmul(b1, make_float2(c, -c));
    b2 = INV ? mulpi(b2) : mulmi(b2);
    b3 = INV ? cmul(b3, make_float2(-c, c)) : cmul(b3, make_float2(-c, -c));
    // DFT4(a) -> X0,X2,X4,X6
    float2 p0 = cadd(a0, a2), p1 = cadd(a1, a3);
    float2 q0 = csub(a0, a2), q1 = csub(a1, a3);
    q1 = INV ? mulpi(q1) : mulmi(q1);
    v[0] = cadd(p0, p1); v[4] = csub(p0, p1);
    v[2] = cadd(q0, q1); v[6] = csub(q0, q1);
    // DFT4(b) -> X1,X3,X5,X7
    float2 r0 = cadd(b0, b2), r1 = cadd(b1, b3);
    float2 s0 = csub(b0, b2), s1 = csub(b1, b3);
    s1 = INV ? mulpi(s1) : mulmi(s1);
    v[1] = cadd(r0, r1); v[5] = csub(r0, r1);
    v[3] = cadd(s0, s1); v[7] = csub(s0, s1);
}

// v[j] *= exp(sign * 2*pi*i * s * j / M), step = 2*pi/M. Power chain from one sincos.
template <bool INV>
__device__ __forceinline__ void twid(float2 v[8], int s, float step) {
    float ang = (INV ? step : -step) * (float)s;
    float sw, cw;
    __sincosf(ang, &sw, &cw);
    float2 w1 = make_float2(cw, sw);
    float2 w = w1;
    v[1] = cmul(v[1], w);
#pragma unroll
    for (int j = 2; j < 8; j++) {
        w = cmul(w, w1);
        v[j] = cmul(v[j], w);
    }
}

#define STEP0 (6.283185307179586f / 4096.0f)
#define STEP1 (6.283185307179586f / 512.0f)
#define STEP2 (6.283185307179586f / 64.0f)

// Forward: natural input (v[r] = x[t + 512 r]) -> digit-reversed register layout.
__device__ __forceinline__ void fft_fwd(float2 v[8], float2* sm, int t) {
    const int d1 = t >> 6, s1 = t & 63;
    const int d2 = t >> 3, s2 = t & 7;

    dft8<false>(v);
    twid<false>(v, t, STEP0);
#pragma unroll
    for (int j = 0; j < 8; j++) sm[pad(j * 512 + t)] = v[j];
    __syncthreads();
#pragma unroll
    for (int r = 0; r < 8; r++) v[r] = sm[pad(d1 * 512 + s1 + 64 * r)];

    dft8<false>(v);
    twid<false>(v, s1, STEP1);
    __syncthreads();
#pragma unroll
    for (int j = 0; j < 8; j++) sm[pad(d1 * 512 + j * 64 + s1)] = v[j];
    __syncthreads();
#pragma unroll
    for (int r = 0; r < 8; r++) v[r] = sm[pad(d2 * 64 + s2 + 8 * r)];

    dft8<false>(v);
    twid<false>(v, s2, STEP2);
    __syncthreads();
#pragma unroll
    for (int j = 0; j < 8; j++) sm[pad(d2 * 64 + j * 8 + s2)] = v[j];
    __syncthreads();
#pragma unroll
    for (int r = 0; r < 8; r++) v[r] = sm[pad(t * 8 + r)];

    dft8<false>(v);   // last stage: s = 0, no twiddle
}

// Inverse: exact mirror of fft_fwd (unscaled; caller multiplies by 1/4096).
// Consumes the digit-reversed layout, produces natural order: y[t+512r] = v[r].
__device__ __forceinline__ void fft_inv(float2 v[8], float2* sm, int t) {
    const int d1 = t >> 6, s1 = t & 63;
    const int d2 = t >> 3, s2 = t & 7;

    dft8<true>(v);
    __syncthreads();
#pragma unroll
    for (int r = 0; r < 8; r++) sm[pad(t * 8 + r)] = v[r];
    __syncthreads();
#pragma unroll
    for (int j = 0; j < 8; j++) v[j] = sm[pad(d2 * 64 + j * 8 + s2)];

    twid<true>(v, s2, STEP2);
    dft8<true>(v);
    __syncthreads();
#pragma unroll
    for (int r = 0; r < 8; r++) sm[pad(d2 * 64 + s2 + 8 * r)] = v[r];
    __syncthreads();
#pragma unroll
    for (int j = 0; j < 8; j++) v[j] = sm[pad(d1 * 512 + j * 64 + s1)];

    twid<true>(v, s1, STEP1);
    dft8<true>(v);
    __syncthreads();
#pragma unroll
    for (int r = 0; r < 8; r++) sm[pad(d1 * 512 + s1 + 64 * r)] = v[r];
    __syncthreads();
#pragma unroll
    for (int j = 0; j < 8; j++) v[j] = sm[pad(j * 512 + t)];

    twid<true>(v, t, STEP0);
    dft8<true>(v);
}

// Kernel A: Kf[h] = FFT(k[h]) stored in pipeline layout g_kf[h*4096 + t*8 + j]
__global__ void __launch_bounds__(NTHR) kf_kernel(const float* __restrict__ k) {
    __shared__ float2 sm[SM_SZ];
    const int h = blockIdx.x;
    const int t = threadIdx.x;
    const float* kp = k + (size_t)h * NFFT;
    float2 v[8];
#pragma unroll
    for (int r = 0; r < 8; r++) v[r] = make_float2(kp[t + 512 * r], 0.0f);
    fft_fwd(v, sm, t);
    float4* out4 = reinterpret_cast<float4*>(g_kf + (size_t)h * NFFT + t * 8);
#pragma unroll
    for (int j = 0; j < 4; j++)
        out4[j] = make_float4(v[2 * j].x, v[2 * j].y, v[2 * j + 1].x, v[2 * j + 1].y);
}

// Kernel B: per (h, batch-pair): z = x[2p,h] + i*x[2p+1,h]; y = ifft(fft(z) * Kf[h])
__global__ void __launch_bounds__(NTHR) conv_kernel(const float* __restrict__ x,
                                                    float* __restrict__ y) {
    __shared__ float2 sm[SM_SZ];
    const int h = blockIdx.x;       // 0..767
    const int bp = blockIdx.y;      // 0..3
    const int t = threadIdx.x;

    const size_t row0 = ((size_t)(2 * bp) * HDIM + h) * NFFT;
    const size_t row1 = row0 + (size_t)HDIM * NFFT;
    const float* x0 = x + row0;
    const float* x1 = x + row1;

    float2 v[8];
#pragma unroll
    for (int r = 0; r < 8; r++) {
        const int idx = t + 512 * r;
        v[r] = make_float2(x0[idx], x1[idx]);
    }

    fft_fwd(v, sm, t);

    // pointwise multiply with Kf[h] in matching digit-reversed layout (4x float4)
    const float4* kf4 = reinterpret_cast<const float4*>(g_kf + (size_t)h * NFFT + t * 8);
    float4 ka = kf4[0], kb = kf4[1], kc = kf4[2], kd = kf4[3];
    v[0] = cmul(v[0], make_float2(ka.x, ka.y));
    v[1] = cmul(v[1], make_float2(ka.z, ka.w));
    v[2] = cmul(v[2], make_float2(kb.x, kb.y));
    v[3] = cmul(v[3], make_float2(kb.z, kb.w));
    v[4] = cmul(v[4], make_float2(kc.x, kc.y));
    v[5] = cmul(v[5], make_float2(kc.z, kc.w));
    v[6] = cmul(v[6], make_float2(kd.x, kd.y));
    v[7] = cmul(v[7], make_float2(kd.z, kd.w));

    fft_inv(v, sm, t);

    float* y0 = y + row0;
    float* y1 = y + row1;
    const float sc = 1.0f / (float)NFFT;
#pragma unroll
    for (int r = 0; r < 8; r++) {
        const int idx = t + 512 * r;
        y0[idx] = v[r].x * sc;
        y1[idx] = v[r].y * sc;
    }
}

extern "C" void kernel_launch(void* const* d_in, const int* in_sizes, int n_in,
                              void* d_out, int out_size) {
    const float* x = (const float*)d_in[0];   // [8, 768, 4096] fp32
    const float* k = (const float*)d_in[1];   // [768, 4096] fp32
    // d_in[2] = n (always 4096), unused
    float* y = (float*)d_out;                 // [8, 768, 4096] fp32

    kf_kernel<<<HDIM, NTHR>>>(k);
    conv_kernel<<<dim3(HDIM, BDIM / 2), NTHR>>>(x, y);
}

// round 3
// speedup vs baseline: 1.2155x; 1.2155x over previous
#include <cuda_runtime.h>

// FFT-based circular convolution:  y[b,h,:] = irfft(rfft(x[b,h]) * rfft(k[h]))
// B=8, H=768, L=N=4096, fp32.
//
// Radix-16 version: 4096 = 16^3, 256 threads, 16 points/thread.
// Only 2 smem exchanges per FFT direction (radix-8 needed 3) -> 33% less
// shared-memory traffic, which ncu showed to be the bottleneck (L1 69.4%).
//
//   * Pack two batch rows (same h) as real+imag of ONE complex FFT (K real ->
//     spectrum conj-symmetric -> ifft((X0+iX1)*K) = y0 + i*y1, no unpack).
//   * Forward DIF leaves digit-reversed layout; Kf computed by identical code
//     path into the same layout; inverse is the exact pipeline mirror ->
//     natural-order output, no bit-reversal pass.
//   * pad16(i)=i+(i>>4): all 4 exchange patterns bank-conflict-free per
//     16-lane phase (verified: p mod 16 distinct in each pattern).

#define NFFT 4096
#define NTHR 256
#define HDIM 768
#define BDIM 8

// K spectra in pipeline layout g_kf[h*4096 + t*16 + j]. 25.2 MB.
__device__ float2 g_kf[HDIM * NFFT];

__device__ __forceinline__ float2 cadd(float2 a, float2 b) {
    return make_float2(a.x + b.x, a.y + b.y);
}
__device__ __forceinline__ float2 csub(float2 a, float2 b) {
    return make_float2(a.x - b.x, a.y - b.y);
}
__device__ __forceinline__ float2 cmul(float2 a, float2 b) {
    return make_float2(fmaf(a.x, b.x, -a.y * b.y), fmaf(a.x, b.y, a.y * b.x));
}
// multiply by -i / +i
__device__ __forceinline__ float2 mulmi(float2 a) { return make_float2(a.y, -a.x); }
__device__ __forceinline__ float2 mulpi(float2 a) { return make_float2(-a.y, a.x); }

// smem padding for radix-16 exchange patterns
__device__ __forceinline__ int pad(int i) { return i + (i >> 4); }
#define SM_SZ (NFFT + (NFFT >> 4))   // 4352 float2 = 34 KB

// 4-point DFT, natural order. INV = conjugated.
template <bool INV>
__device__ __forceinline__ void dft4(float2& a, float2& b, float2& c, float2& d) {
    float2 t0 = cadd(a, c), t1 = csub(a, c);
    float2 t2 = cadd(b, d), t3 = csub(b, d);
    t3 = INV ? mulpi(t3) : mulmi(t3);
    a = cadd(t0, t2);
    b = cadd(t1, t3);
    c = csub(t0, t2);
    d = csub(t1, t3);
}

// 16-point DFT, natural in/out, via 4x4 decomposition.
// n = 4*n1 + n2, k = k1 + 4*k2:
//   y_{n2}[k1] = DFT4_{n1} x[4n1+n2];  y *= W16^{n2 k1};  X[k1+4k2] = DFT4_{n2} y.
template <bool INV>
__device__ __forceinline__ void dft16(float2 v[16]) {
    const float C1 = 0.9238795325112867f;   // cos(pi/8)
    const float S1 = 0.3826834323650898f;   // sin(pi/8)
    const float C2 = 0.7071067811865476f;   // cos(pi/4)
    float2 w[16];
#pragma unroll
    for (int n2 = 0; n2 < 4; n2++) {
        float2 a = v[n2], b = v[4 + n2], c = v[8 + n2], d = v[12 + n2];
        dft4<INV>(a, b, c, d);
        w[n2 * 4 + 0] = a; w[n2 * 4 + 1] = b; w[n2 * 4 + 2] = c; w[n2 * 4 + 3] = d;
    }
    // twiddle w[n2*4+k1] *= W16^{n2*k1}  (fwd values; conj for INV)
#define TWC(i, re, im) w[i] = cmul(w[i], make_float2((re), INV ? -(im) : (im)))
    TWC(5,  C1, -S1);            // n2=1,k1=1: W16^1
    TWC(6,  C2, -C2);            // n2=1,k1=2: W16^2
    TWC(7,  S1, -C1);            // n2=1,k1=3: W16^3
    TWC(9,  C2, -C2);            // n2=2,k1=1: W16^2
    w[10] = INV ? mulpi(w[10]) : mulmi(w[10]);   // n2=2,k1=2: W16^4 = -i
    TWC(11, -C2, -C2);           // n2=2,k1=3: W16^6
    TWC(13,  S1, -C1);           // n2=3,k1=1: W16^3
    TWC(14, -C2, -C2);           // n2=3,k1=2: W16^6
    TWC(15, -C1,  S1);           // n2=3,k1=3: W16^9
#undef TWC
#pragma unroll
    for (int k1 = 0; k1 < 4; k1++) {
        float2 a = w[k1], b = w[4 + k1], c = w[8 + k1], d = w[12 + k1];
        dft4<INV>(a, b, c, d);
        v[k1 + 0] = a; v[k1 + 4] = b; v[k1 + 8] = c; v[k1 + 12] = d;
    }
}

// v[j] *= exp(sign * 2*pi*i * s * j / M), j=1..15. Two sincos (w1, w8) + short chains.
template <bool INV>
__device__ __forceinline__ void twid16(float2 v[16], int s, float step) {
    float ang = (INV ? step : -step) * (float)s;
    float sw, cw;
    __sincosf(ang, &sw, &cw);
    float2 w1 = make_float2(cw, sw);
    float s8, c8;
    __sincosf(8.0f * ang, &s8, &c8);
    float2 w8 = make_float2(c8, s8);
    float2 w = w1;
    v[1] = cmul(v[1], w);
#pragma unroll
    for (int j = 2; j < 8; j++) { w = cmul(w, w1); v[j] = cmul(v[j], w); }
    v[8] = cmul(v[8], w8);
    w = w8;
#pragma unroll
    for (int j = 9; j < 16; j++) { w = cmul(w, w1); v[j] = cmul(v[j], w); }
}

#define STEP0 (6.283185307179586f / 4096.0f)
#define STEP1 (6.283185307179586f / 256.0f)

// Forward: natural input (v[r] = x[t + 256 r]) -> digit-reversed register layout
// (pipeline layout element t*16+j lives in v[j] of thread t).
__device__ __forceinline__ void fft_fwd(float2 v[16], float2* sm, int t) {
    const int d1 = t >> 4, s1 = t & 15;

    dft16<false>(v);
    twid16<false>(v, t, STEP0);
#pragma unroll
    for (int j = 0; j < 16; j++) sm[pad(j * 256 + t)] = v[j];
    __syncthreads();
#pragma unroll
    for (int r = 0; r < 16; r++) v[r] = sm[pad(d1 * 256 + s1 + 16 * r)];

    dft16<false>(v);
    twid16<false>(v, s1, STEP1);
    __syncthreads();
#pragma unroll
    for (int j = 0; j < 16; j++) sm[pad(d1 * 256 + j * 16 + s1)] = v[j];
    __syncthreads();
#pragma unroll
    for (int r = 0; r < 16; r++) v[r] = sm[pad(t * 16 + r)];

    dft16<false>(v);   // last stage: local index 0, no twiddle
}

// Inverse: exact mirror (unscaled; caller applies 1/4096). Digit-reversed in,
// natural order out: y[t + 256 r] = v[r].
__device__ __forceinline__ void fft_inv(float2 v[16], float2* sm, int t) {
    const int d1 = t >> 4, s1 = t & 15;

    dft16<true>(v);
    __syncthreads();
#pragma unroll
    for (int r = 0; r < 16; r++) sm[pad(t * 16 + r)] = v[r];
    __syncthreads();
#pragma unroll
    for (int j = 0; j < 16; j++) v[j] = sm[pad(d1 * 256 + j * 16 + s1)];

    twid16<true>(v, s1, STEP1);
    dft16<true>(v);
    __syncthreads();
#pragma unroll
    for (int r = 0; r < 16; r++) sm[pad(d1 * 256 + s1 + 16 * r)] = v[r];
    __syncthreads();
#pragma unroll
    for (int j = 0; j < 16; j++) v[j] = sm[pad(j * 256 + t)];

    twid16<true>(v, t, STEP0);
    dft16<true>(v);
}

// Kernel A: Kf[h] = FFT(k[h]) in pipeline layout g_kf[h*4096 + t*16 + j]
__global__ void __launch_bounds__(NTHR) kf_kernel(const float* __restrict__ k) {
    __shared__ float2 sm[SM_SZ];
    const int h = blockIdx.x;
    const int t = threadIdx.x;
    const float* kp = k + (size_t)h * NFFT;
    float2 v[16];
#pragma unroll
    for (int r = 0; r < 16; r++) v[r] = make_float2(kp[t + 256 * r], 0.0f);
    fft_fwd(v, sm, t);
    float4* out4 = reinterpret_cast<float4*>(g_kf + (size_t)h * NFFT + t * 16);
#pragma unroll
    for (int j = 0; j < 8; j++)
        out4[j] = make_float4(v[2 * j].x, v[2 * j].y, v[2 * j + 1].x, v[2 * j + 1].y);
}

// Kernel B: per (h, batch-pair): z = x[2p,h] + i*x[2p+1,h]; y = ifft(fft(z)*Kf[h])
__global__ void __launch_bounds__(NTHR) conv_kernel(const float* __restrict__ x,
                                                    float* __restrict__ y) {
    __shared__ float2 sm[SM_SZ];
    const int h = blockIdx.x;       // 0..767
    const int bp = blockIdx.y;      // 0..3
    const int t = threadIdx.x;

    const size_t row0 = ((size_t)(2 * bp) * HDIM + h) * NFFT;
    const size_t row1 = row0 + (size_t)HDIM * NFFT;
    const float* x0 = x + row0;
    const float* x1 = x + row1;

    float2 v[16];
#pragma unroll
    for (int r = 0; r < 16; r++) {
        const int idx = t + 256 * r;
        v[r] = make_float2(x0[idx], x1[idx]);
    }

    fft_fwd(v, sm, t);

    // pointwise multiply with Kf[h] in matching digit-reversed layout (8x float4)
    const float4* kf4 = reinterpret_cast<const float4*>(g_kf + (size_t)h * NFFT + t * 16);
#pragma unroll
    for (int j = 0; j < 8; j++) {
        float4 kk = kf4[j];
        v[2 * j]     = cmul(v[2 * j],     make_float2(kk.x, kk.y));
        v[2 * j + 1] = cmul(v[2 * j + 1], make_float2(kk.z, kk.w));
    }

    fft_inv(v, sm, t);

    float* y0 = y + row0;
    float* y1 = y + row1;
    const float sc = 1.0f / (float)NFFT;
#pragma unroll
    for (int r = 0; r < 16; r++) {
        const int idx = t + 256 * r;
        y0[idx] = v[r].x * sc;
        y1[idx] = v[r].y * sc;
    }
}

extern "C" void kernel_launch(void* const* d_in, const int* in_sizes, int n_in,
                              void* d_out, int out_size) {
    const float* x = (const float*)d_in[0];   // [8, 768, 4096] fp32
    const float* k = (const float*)d_in[1];   // [768, 4096] fp32
    // d_in[2] = n (always 4096), unused
    float* y = (float*)d_out;                 // [8, 768, 4096] fp32

    kf_kernel<<<HDIM, NTHR>>>(k);
    conv_kernel<<<dim3(HDIM, BDIM / 2), NTHR>>>(x, y);
}